// round 7
// baseline (speedup 1.0000x reference)
#include <cuda_runtime.h>
#include <math.h>
#include <stdint.h>

#define BB 2
#define II 768
#define CA 768
#define CS 384
#define CZ 128
#define HH 16
#define DD 48
#define HC 768
#define QS 3072             /* packed qkvg row stride */
#define MM (BB*II)          /* 1536 rows */
#define EPSV 1e-5f

/* ---------------- scratch (no allocations allowed) ---------------- */
__device__ float g_aln[MM * CA];
__device__ float g_sln[MM * CS];
__device__ float g_gate1[MM * CA];
__device__ float g_a[MM * CA];
__device__ float g_Wqkvg[CA * QS];                      /* packed Wq|Wk|Wv|Wg */
__device__ float g_qkvg[MM * QS];                       /* packed q|k|v|g    */
__device__ float g_gate2[MM * CA];
__device__ float g_o[MM * HC];
__device__ float g_bias[(size_t)BB * HH * II * II];     /* [b,h,i,j] 75.5 MB */

/* ---------------- tf32 helpers ---------------- */
__device__ __forceinline__ float tf32_rna(float x) {
    uint32_t u;
    asm("cvt.rna.tf32.f32 %0, %1;" : "=r"(u) : "f"(x));
    return __uint_as_float(u);
}
__device__ __forceinline__ void mma_tf32(float* c, const float* a, const float* b) {
    asm volatile(
        "mma.sync.aligned.m16n8k8.row.col.f32.tf32.tf32.f32 "
        "{%0,%1,%2,%3}, {%4,%5,%6,%7}, {%8,%9}, {%0,%1,%2,%3};"
        : "+f"(c[0]), "+f"(c[1]), "+f"(c[2]), "+f"(c[3])
        : "r"(__float_as_uint(a[0])), "r"(__float_as_uint(a[1])),
          "r"(__float_as_uint(a[2])), "r"(__float_as_uint(a[3])),
          "r"(__float_as_uint(b[0])), "r"(__float_as_uint(b[1])));
}

/* ---------------- weight packing: [768][768]x4 -> [768][3072] ------------ */
__global__ __launch_bounds__(256) void pack_w(const float* __restrict__ Wq,
                                              const float* __restrict__ Wk,
                                              const float* __restrict__ Wv,
                                              const float* __restrict__ Wg,
                                              float* __restrict__ P)
{
    int idx = blockIdx.x * 256 + threadIdx.x;       /* over CA*HC/4 float4s */
    int r = idx / (HC / 4), c4 = idx % (HC / 4);
    float4 q4 = ((const float4*)Wq)[idx];
    float4 k4 = ((const float4*)Wk)[idx];
    float4 v4 = ((const float4*)Wv)[idx];
    float4 g4 = ((const float4*)Wg)[idx];
    float4* row = (float4*)(P + (size_t)r * QS);
    row[c4]                 = q4;
    row[c4 + HC / 4]        = k4;
    row[c4 + 2 * (HC / 4)]  = v4;
    row[c4 + 3 * (HC / 4)]  = g4;
}

/* ---------------- LayerNorm (block per row) ---------------- */
template<int W, bool AFFINE>
__global__ __launch_bounds__(256) void ln_kernel(const float* __restrict__ x,
                                                 const float* __restrict__ w,
                                                 const float* __restrict__ bvec,
                                                 float* __restrict__ y)
{
    int row = blockIdx.x;
    const float* xr = x + (size_t)row * W;
    float* yr = y + (size_t)row * W;
    float vals[(W + 255) / 256];
    float s = 0.f, ss = 0.f;
    int cnt = 0;
    for (int c = threadIdx.x; c < W; c += 256) {
        float v = xr[c];
        vals[cnt++] = v;
        s += v; ss += v * v;
    }
    __shared__ float sh1[8], sh2[8];
    int lane = threadIdx.x & 31, wid = threadIdx.x >> 5;
#pragma unroll
    for (int off = 16; off; off >>= 1) {
        s  += __shfl_xor_sync(0xffffffffu, s,  off);
        ss += __shfl_xor_sync(0xffffffffu, ss, off);
    }
    if (lane == 0) { sh1[wid] = s; sh2[wid] = ss; }
    __syncthreads();
    if (threadIdx.x == 0) {
        float ts = 0.f, tss = 0.f;
        for (int q = 0; q < 8; q++) { ts += sh1[q]; tss += sh2[q]; }
        sh1[0] = ts; sh2[0] = tss;
    }
    __syncthreads();
    s = sh1[0]; ss = sh2[0];
    float mean = s * (1.0f / W);
    float var  = ss * (1.0f / W) - mean * mean;
    float inv  = rsqrtf(var + EPSV);
    cnt = 0;
    for (int c = threadIdx.x; c < W; c += 256) {
        float v = (vals[cnt++] - mean) * inv;
        if (AFFINE) v = v * w[c] + bvec[c];
        yr[c] = v;
    }
}

/* ---------------- 3xTF32 tensor-core GEMM ----------------
   Block tile 128x128, 8 warps of 32(m) x 64(n), mma.m16n8k8.
   C = A@B with 3-term tf32 split (hi*lo + lo*hi + hi*hi) => fp32-grade accuracy.
   EPI: 3 sigmoid(.+bias[n]) | 4 .*e1[m,n] | 5 qkvg segments | 6 .+e1*e2 */
template<int EPI>
__global__ __launch_bounds__(256) void tf32_gemm(const float* __restrict__ A,
                                                 const float* __restrict__ Bm,
                                                 float* __restrict__ C,
                                                 const float* __restrict__ bias,
                                                 const float* __restrict__ e1,
                                                 const float* __restrict__ e2,
                                                 int M, int N, int K)
{
    __shared__ float As_h[16][136];
    __shared__ float As_l[16][136];
    __shared__ float Bs_h[16][136];
    __shared__ float Bs_l[16][136];

    int m0 = blockIdx.y * 128, n0 = blockIdx.x * 128;
    int tid = threadIdx.x, lane = tid & 31, wid = tid >> 5;
    int wm0 = (wid & 3) * 32, wn0 = (wid >> 2) * 64;
    int g = lane >> 2, tg = lane & 3;

    float acc[2][8][4];
#pragma unroll
    for (int mf = 0; mf < 2; mf++)
#pragma unroll
        for (int nf = 0; nf < 8; nf++)
#pragma unroll
            for (int r = 0; r < 4; r++) acc[mf][nf][r] = 0.f;

    int arow = tid >> 1;
    int bkr = tid >> 4;

    for (int k0 = 0; k0 < K; k0 += 16) {
        /* stage A (row-major -> k-major hi/lo) */
#pragma unroll
        for (int u = 0; u < 2; u++) {
            int c4 = (tid & 1) * 2 + u;
            float4 av = *(const float4*)&A[(size_t)(m0 + arow) * K + k0 + c4 * 4];
            const float* ap = &av.x;
#pragma unroll
            for (int j = 0; j < 4; j++) {
                float x = ap[j];
                float h = tf32_rna(x);
                As_h[c4 * 4 + j][arow] = h;
                As_l[c4 * 4 + j][arow] = tf32_rna(x - h);
            }
        }
        /* stage B (already k-major) */
#pragma unroll
        for (int u = 0; u < 2; u++) {
            int c4 = (tid & 15) + u * 16;
            float4 bv = *(const float4*)&Bm[(size_t)(k0 + bkr) * N + n0 + c4 * 4];
            float4 bh, bl;
            bh.x = tf32_rna(bv.x); bl.x = tf32_rna(bv.x - bh.x);
            bh.y = tf32_rna(bv.y); bl.y = tf32_rna(bv.y - bh.y);
            bh.z = tf32_rna(bv.z); bl.z = tf32_rna(bv.z - bh.z);
            bh.w = tf32_rna(bv.w); bl.w = tf32_rna(bv.w - bh.w);
            *(float4*)&Bs_h[bkr][c4 * 4] = bh;
            *(float4*)&Bs_l[bkr][c4 * 4] = bl;
        }
        __syncthreads();

#pragma unroll
        for (int kk = 0; kk < 16; kk += 8) {
            float a_h[2][4], a_l[2][4];
#pragma unroll
            for (int mf = 0; mf < 2; mf++) {
                int mr = wm0 + mf * 16 + g;
                a_h[mf][0] = As_h[kk + tg][mr];
                a_h[mf][1] = As_h[kk + tg][mr + 8];
                a_h[mf][2] = As_h[kk + tg + 4][mr];
                a_h[mf][3] = As_h[kk + tg + 4][mr + 8];
                a_l[mf][0] = As_l[kk + tg][mr];
                a_l[mf][1] = As_l[kk + tg][mr + 8];
                a_l[mf][2] = As_l[kk + tg + 4][mr];
                a_l[mf][3] = As_l[kk + tg + 4][mr + 8];
            }
#pragma unroll
            for (int nf = 0; nf < 8; nf++) {
                float b_h[2], b_l[2];
                int nc = wn0 + nf * 8 + g;
                b_h[0] = Bs_h[kk + tg][nc];
                b_h[1] = Bs_h[kk + tg + 4][nc];
                b_l[0] = Bs_l[kk + tg][nc];
                b_l[1] = Bs_l[kk + tg + 4][nc];
#pragma unroll
                for (int mf = 0; mf < 2; mf++) {
                    mma_tf32(acc[mf][nf], a_h[mf], b_l);
                    mma_tf32(acc[mf][nf], a_l[mf], b_h);
                    mma_tf32(acc[mf][nf], a_h[mf], b_h);
                }
            }
        }
        __syncthreads();
    }

    /* epilogue: c0,c1 -> (row, 2tg..2tg+1), c2,c3 -> (row+8, same) */
#pragma unroll
    for (int mf = 0; mf < 2; mf++) {
#pragma unroll
        for (int half = 0; half < 2; half++) {
            int m = m0 + wm0 + mf * 16 + g + half * 8;
#pragma unroll
            for (int nf = 0; nf < 8; nf++) {
                int n = n0 + wn0 + nf * 8 + 2 * tg;
                float v0 = acc[mf][nf][half * 2 + 0];
                float v1 = acc[mf][nf][half * 2 + 1];
                if (EPI == 3) {
                    v0 = 1.f / (1.f + __expf(-(v0 + bias[n])));
                    v1 = 1.f / (1.f + __expf(-(v1 + bias[n + 1])));
                } else if (EPI == 4) {
                    const float2 ev = *(const float2*)&e1[(size_t)m * N + n];
                    v0 *= ev.x; v1 *= ev.y;
                } else if (EPI == 5) {
                    if (n < HC) { v0 += bias[n]; v1 += bias[n + 1]; }
                    else if (n >= 3 * HC) {
                        v0 = 1.f / (1.f + __expf(-v0));
                        v1 = 1.f / (1.f + __expf(-v1));
                    }
                } else if (EPI == 6) {
                    const float2 x1 = *(const float2*)&e1[(size_t)m * N + n];
                    const float2 x2 = *(const float2*)&e2[(size_t)m * N + n];
                    v0 += x1.x * x2.x; v1 += x1.y * x2.y;
                }
                *(float2*)&C[(size_t)m * N + n] = make_float2(v0, v1);
            }
        }
    }
}

/* ---------------- pair bias: LN(z,128) @ Wb + beta -> bias[b,h,i,j] ---- */
__global__ __launch_bounds__(1024) void pairbias_kernel(const float* __restrict__ z,
                                                        const float* __restrict__ beta,
                                                        const float* __restrict__ lnw,
                                                        const float* __restrict__ lnb,
                                                        const float* __restrict__ Wb,
                                                        float* __restrict__ S)
{
    __shared__ float sWbT[16][128];
    __shared__ float sw[128], sb[128];
    __shared__ float sbeta[512];
    __shared__ float stage[16][32];
    int b = blockIdx.z, i = blockIdx.y, jt = blockIdx.x;
    int tid = threadIdx.x;
    for (int idx = tid; idx < 2048; idx += 1024) {
        int c = idx >> 4, h = idx & 15;           /* Wb row-major [128][16] */
        sWbT[h][c] = Wb[idx];
    }
    if (tid < 128) { sw[tid] = lnw[tid]; sb[tid] = lnb[tid]; }
    if (tid < 512) {
        size_t bo = ((size_t)(b * II + i) * II + jt * 32) * HH;
        sbeta[tid] = beta[bo + tid];
    }
    __syncthreads();
    int w = tid >> 5, lane = tid & 31;
    int j = jt * 32 + w;
    const float4 z4 = *(const float4*)(z + ((size_t)(b * II + i) * II + j) * CZ + lane * 4);
    float s  = z4.x + z4.y + z4.z + z4.w;
    float ss = z4.x * z4.x + z4.y * z4.y + z4.z * z4.z + z4.w * z4.w;
#pragma unroll
    for (int off = 16; off; off >>= 1) {
        s  += __shfl_xor_sync(0xffffffffu, s,  off);
        ss += __shfl_xor_sync(0xffffffffu, ss, off);
    }
    float mean = s * (1.f / CZ);
    float var  = ss * (1.f / CZ) - mean * mean;
    float inv  = rsqrtf(var + EPSV);
    int c0 = lane * 4;
    float y0 = (z4.x - mean) * inv * sw[c0 + 0] + sb[c0 + 0];
    float y1 = (z4.y - mean) * inv * sw[c0 + 1] + sb[c0 + 1];
    float y2 = (z4.z - mean) * inv * sw[c0 + 2] + sb[c0 + 2];
    float y3 = (z4.w - mean) * inv * sw[c0 + 3] + sb[c0 + 3];
    float acc[16];
#pragma unroll
    for (int h = 0; h < 16; h++) {
        float4 wv = *(const float4*)&sWbT[h][c0];
        acc[h] = y0 * wv.x + y1 * wv.y + y2 * wv.z + y3 * wv.w;
    }
    const unsigned FM = 0xffffffffu;
    bool b4 = (lane & 16) != 0;
    float t8[8];
#pragma unroll
    for (int h = 0; h < 8; h++) {
        float keep = b4 ? acc[h + 8] : acc[h];
        float send = b4 ? acc[h] : acc[h + 8];
        t8[h] = keep + __shfl_xor_sync(FM, send, 16);
    }
    bool b3 = (lane & 8) != 0;
    float t4[4];
#pragma unroll
    for (int h = 0; h < 4; h++) {
        float keep = b3 ? t8[h + 4] : t8[h];
        float send = b3 ? t8[h] : t8[h + 4];
        t4[h] = keep + __shfl_xor_sync(FM, send, 8);
    }
    bool b2 = (lane & 4) != 0;
    float t2[2];
#pragma unroll
    for (int h = 0; h < 2; h++) {
        float keep = b2 ? t4[h + 2] : t4[h];
        float send = b2 ? t4[h] : t4[h + 2];
        t2[h] = keep + __shfl_xor_sync(FM, send, 4);
    }
    bool b1 = (lane & 2) != 0;
    float keep1 = b1 ? t2[1] : t2[0];
    float send1 = b1 ? t2[0] : t2[1];
    float t1 = keep1 + __shfl_xor_sync(FM, send1, 2);
    t1 += __shfl_xor_sync(FM, t1, 1);
    if ((lane & 1) == 0) stage[(lane >> 1) & 15][w] = t1;
    __syncthreads();
    if (tid < 512) {
        int h = tid >> 5, jj = tid & 31;
        S[((size_t)(b * HH + h) * II + i) * II + jt * 32 + jj] =
            stage[h][jj] + sbeta[jj * HH + h];
    }
}

/* ---------------- fused flash attention ---------------- */
__global__ __launch_bounds__(256) void flash_kernel(const float* __restrict__ qkvg,
                                                    const float* __restrict__ bias,
                                                    float* __restrict__ O)
{
    __shared__ float Qs[DD][68];
    __shared__ float Ks[DD][68];
    __shared__ float Vs[64][52];
    __shared__ float sP[64][68];
    __shared__ float sm[64], sl[64], srs[64];
    int b = blockIdx.z, h = blockIdx.y, i0 = blockIdx.x * 64;
    int tid = threadIdx.x, tx = tid & 15, ty = tid >> 4;

#pragma unroll
    for (int e = 0; e < 3; e++) {
        int idx = tid + e * 256;
        int row = idx / 12, c4 = idx % 12;
        float4 qv = *(const float4*)&qkvg[(size_t)(b * II + i0 + row) * QS + h * DD + c4 * 4];
        Qs[c4 * 4 + 0][row] = qv.x;
        Qs[c4 * 4 + 1][row] = qv.y;
        Qs[c4 * 4 + 2][row] = qv.z;
        Qs[c4 * 4 + 3][row] = qv.w;
    }
    if (tid < 64) { sm[tid] = -1e30f; sl[tid] = 0.f; }

    float oacc[4][3] = {};
    const float kscale = 0.14433756729740643f;
    const float* bb = bias + ((size_t)((b * HH + h) * II + i0)) * II;

    for (int j0 = 0; j0 < II; j0 += 64) {
        __syncthreads();
#pragma unroll
        for (int e = 0; e < 3; e++) {
            int idx = tid + e * 256;
            int row = idx / 12, c4 = idx % 12;
            float4 kv = *(const float4*)&qkvg[(size_t)(b * II + j0 + row) * QS + HC + h * DD + c4 * 4];
            Ks[c4 * 4 + 0][row] = kv.x;
            Ks[c4 * 4 + 1][row] = kv.y;
            Ks[c4 * 4 + 2][row] = kv.z;
            Ks[c4 * 4 + 3][row] = kv.w;
            float4 vv = *(const float4*)&qkvg[(size_t)(b * II + j0 + row) * QS + 2 * HC + h * DD + c4 * 4];
            *(float4*)&Vs[row][c4 * 4] = vv;
        }
        __syncthreads();

        float s[4][4] = {};
#pragma unroll
        for (int d = 0; d < DD; d++) {
            float4 qa = *(const float4*)&Qs[d][ty * 4];
            float4 kb = *(const float4*)&Ks[d][tx * 4];
            float qv[4] = {qa.x, qa.y, qa.z, qa.w};
            float kv[4] = {kb.x, kb.y, kb.z, kb.w};
#pragma unroll
            for (int i2 = 0; i2 < 4; i2++)
#pragma unroll
                for (int j2 = 0; j2 < 4; j2++)
                    s[i2][j2] += qv[i2] * kv[j2];
        }
        const unsigned FM = 0xffffffffu;
#pragma unroll
        for (int i2 = 0; i2 < 4; i2++) {
            int row = ty * 4 + i2;
            float4 bv = *(const float4*)&bb[(size_t)row * II + j0 + tx * 4];
            s[i2][0] = s[i2][0] * kscale + bv.x;
            s[i2][1] = s[i2][1] * kscale + bv.y;
            s[i2][2] = s[i2][2] * kscale + bv.z;
            s[i2][3] = s[i2][3] * kscale + bv.w;
            float mloc = fmaxf(fmaxf(s[i2][0], s[i2][1]), fmaxf(s[i2][2], s[i2][3]));
#pragma unroll
            for (int off = 8; off; off >>= 1)
                mloc = fmaxf(mloc, __shfl_xor_sync(FM, mloc, off));
            float m_old = sm[row];
            float m_new = fmaxf(m_old, mloc);
            float rsum = 0.f;
#pragma unroll
            for (int j2 = 0; j2 < 4; j2++) {
                float p = __expf(s[i2][j2] - m_new);
                s[i2][j2] = p;
                rsum += p;
            }
#pragma unroll
            for (int off = 8; off; off >>= 1)
                rsum += __shfl_xor_sync(FM, rsum, off);
            *(float4*)&sP[row][tx * 4] = make_float4(s[i2][0], s[i2][1], s[i2][2], s[i2][3]);
            if (tx == 0) {
                float f = __expf(m_old - m_new);
                srs[row] = f;
                sl[row] = sl[row] * f + rsum;
                sm[row] = m_new;
            }
        }
        __syncthreads();

#pragma unroll
        for (int i2 = 0; i2 < 4; i2++) {
            float f = srs[ty * 4 + i2];
            oacc[i2][0] *= f; oacc[i2][1] *= f; oacc[i2][2] *= f;
        }
#pragma unroll 4
        for (int jk = 0; jk < 64; jk++) {
            float v0 = Vs[jk][tx * 3 + 0];
            float v1 = Vs[jk][tx * 3 + 1];
            float v2 = Vs[jk][tx * 3 + 2];
#pragma unroll
            for (int i2 = 0; i2 < 4; i2++) {
                float p = sP[ty * 4 + i2][jk];
                oacc[i2][0] += p * v0;
                oacc[i2][1] += p * v1;
                oacc[i2][2] += p * v2;
            }
        }
    }
    __syncthreads();
#pragma unroll
    for (int i2 = 0; i2 < 4; i2++) {
        int row = ty * 4 + i2;
        float inv = 1.f / sl[row];
#pragma unroll
        for (int t = 0; t < 3; t++) {
            int d = tx * 3 + t;
            size_t gi = (size_t)(b * II + i0 + row) * QS + 3 * HC + h * DD + d;
            O[(size_t)(b * II + i0 + row) * HC + h * DD + d] = oacc[i2][t] * inv * qkvg[gi];
        }
    }
}

/* ---------------- host launcher ---------------- */
extern "C" void kernel_launch(void* const* d_in, const int* in_sizes, int n_in,
                              void* d_out, int out_size)
{
    (void)in_sizes; (void)n_in; (void)out_size;
    const float* a_i  = (const float*)d_in[0];
    const float* s_i  = (const float*)d_in[1];
    const float* z_ij = (const float*)d_in[2];
    const float* beta = (const float*)d_in[3];
    const float* lnsw = (const float*)d_in[4];
    const float* lnsb = (const float*)d_in[5];
    const float* Ws   = (const float*)d_in[6];
    const float* bs   = (const float*)d_in[7];
    const float* Wnb  = (const float*)d_in[8];
    const float* Wq   = (const float*)d_in[9];
    const float* bq   = (const float*)d_in[10];
    const float* Wk   = (const float*)d_in[11];
    const float* Wv   = (const float*)d_in[12];
    const float* lnbw = (const float*)d_in[13];
    const float* lnbb = (const float*)d_in[14];
    const float* Wb   = (const float*)d_in[15];
    const float* Wg   = (const float*)d_in[16];
    const float* Wo   = (const float*)d_in[17];
    const float* Wso  = (const float*)d_in[18];
    const float* bso  = (const float*)d_in[19];
    float* out = (float*)d_out;

    float *aln, *sln, *gate1, *a, *wpk, *qkvg, *gate2, *o, *biasb;
    cudaGetSymbolAddress((void**)&aln,   g_aln);
    cudaGetSymbolAddress((void**)&sln,   g_sln);
    cudaGetSymbolAddress((void**)&gate1, g_gate1);
    cudaGetSymbolAddress((void**)&a,     g_a);
    cudaGetSymbolAddress((void**)&wpk,   g_Wqkvg);
    cudaGetSymbolAddress((void**)&qkvg,  g_qkvg);
    cudaGetSymbolAddress((void**)&gate2, g_gate2);
    cudaGetSymbolAddress((void**)&o,     g_o);
    cudaGetSymbolAddress((void**)&biasb, g_bias);

    /* 1: weight packing */
    pack_w<<<(CA * HC / 4) / 256, 256>>>(Wq, Wk, Wv, Wg, wpk);

    /* 2,3: LayerNorms */
    ln_kernel<CA, false><<<MM, 256>>>(a_i, nullptr, nullptr, aln);
    ln_kernel<CS, true ><<<MM, 256>>>(s_i, lnsw, lnsb, sln);

    /* 4: gate1 = sigmoid(sln@Ws + bs) */
    tf32_gemm<3><<<dim3(CA / 128, MM / 128), 256>>>(sln, Ws, gate1, bs, nullptr, nullptr, MM, CA, CS);

    /* 5: a = sln@Wnb + gate1 * aln */
    tf32_gemm<6><<<dim3(CA / 128, MM / 128), 256>>>(sln, Wnb, a, nullptr, gate1, aln, MM, CA, CS);

    /* 6: fused q|k|v|g projection GEMM: [1536,768]@[768,3072]  (ncu capture slot) */
    tf32_gemm<5><<<dim3(QS / 128, MM / 128), 256>>>(a, wpk, qkvg, bq, nullptr, nullptr, MM, QS, CA);

    /* 7: output gate from RAW s_i */
    tf32_gemm<3><<<dim3(CA / 128, MM / 128), 256>>>(s_i, Wso, gate2, bso, nullptr, nullptr, MM, CA, CS);

    /* 8: pair bias -> bias[b,h,i,j] */
    pairbias_kernel<<<dim3(II / 32, II, BB), 1024>>>(z_ij, beta, lnbw, lnbb, Wb, biasb);

    /* 9: fused attention */
    flash_kernel<<<dim3(II / 64, HH, BB), 256>>>(qkvg, biasb, o);

    /* 10: out = gate2 * (o @ Wo) */
    tf32_gemm<4><<<dim3(CA / 128, MM / 128), 256>>>(o, Wo, out, nullptr, gate2, nullptr, MM, CA, HC);
}